// round 16
// baseline (speedup 1.0000x reference)
#include <cuda_runtime.h>
#include <math_constants.h>

// Problem constants
constexpr int B_   = 4;
constexpr int S_   = 4096;
constexpr int D_   = 1024;
constexpr int M_   = B_ * S_;      // 16384 fused batch*seq rows for QKV

// GEMM tiling
constexpr int BM = 128;
constexpr int BN = 128;
constexpr int BK = 16;
constexpr int TM = 8;
constexpr int TN = 8;
constexpr int NTHREADS = (BM / TM) * (BN / TN);   // 256

// Static device scratch (allocation-free rule): Q,K,V = 3*64MB, P(scores) = 256MB
__device__ float g_Q[(size_t)M_ * D_];
__device__ float g_K[(size_t)M_ * D_];
__device__ float g_V[(size_t)M_ * D_];
__device__ float g_P[(size_t)B_ * S_ * S_];

// ---------------------------------------------------------------------------
// Generic fp32 SGEMM, C = A * op(B)
//   B_ROWS_ARE_N = true  : B is [N, K] row-major (K contiguous)  -> C=A*B^T (NT)
//   B_ROWS_ARE_N = false : B is [K, N] row-major (N contiguous)  -> C=A*B  (NN)
//   TRI_SKIP  : skip whole tiles strictly above the block diagonal (scores)
//   CAUSAL_K  : truncate K loop at (tileM+1)*BM (context GEMM; P is zero above diag)
// blockIdx.z = batch with element strides sA/sB/sC.
// Requires M%BM==0, N%BN==0, K%BK==0, 16B-aligned rows (all true here).
// ---------------------------------------------------------------------------
template<bool B_ROWS_ARE_N, bool TRI_SKIP, bool CAUSAL_K>
__global__ __launch_bounds__(NTHREADS, 2)
void sgemm_kernel(const float* __restrict__ gA, const float* __restrict__ gB,
                  float* __restrict__ gC,
                  int M, int N, int K,
                  size_t sA, size_t sB, size_t sC)
{
    const int tileN = blockIdx.x;
    const int tileM = blockIdx.y;
    if (TRI_SKIP && tileN > tileM) return;   // uniform per-CTA, safe before syncs

    const float* A = gA + (size_t)blockIdx.z * sA;
    const float* Bm = gB + (size_t)blockIdx.z * sB;
    float*       C = gC + (size_t)blockIdx.z * sC;

    int Keff = K;
    if (CAUSAL_K) {
        int lim = (tileM + 1) * BM;
        if (lim < Keff) Keff = lim;
    }

    __shared__ float As[BK][BM];
    __shared__ float Bs[BK][BN];

    const int tid = threadIdx.x;
    const int tx  = tid % (BN / TN);   // 0..15
    const int ty  = tid / (BN / TN);   // 0..15

    // K-major tile load mapping (A always; B when B_ROWS_ARE_N)
    const int lrow = tid >> 2;         // 0..63
    const int lcol = (tid & 3) * 4;    // 0,4,8,12

    // N-contiguous B load mapping (NN mode)
    const int nrow = tid >> 5;         // 0..7
    const int ncol = (tid & 31) * 4;   // 0..124

    const float* Arow0 = A + (size_t)(tileM * BM) * K;
    const float* Brow0 = B_ROWS_ARE_N ? (Bm + (size_t)(tileN * BN) * K) : Bm;

    float acc[TM][TN];
    #pragma unroll
    for (int i = 0; i < TM; ++i)
        #pragma unroll
        for (int j = 0; j < TN; ++j)
            acc[i][j] = 0.0f;

    for (int k0 = 0; k0 < Keff; k0 += BK) {
        // --- stage A (transposed into As[k][m]) ---
        #pragma unroll
        for (int r = 0; r < 2; ++r) {
            const int m = lrow + r * 64;
            float4 v = *reinterpret_cast<const float4*>(Arow0 + (size_t)m * K + k0 + lcol);
            As[lcol + 0][m] = v.x;
            As[lcol + 1][m] = v.y;
            As[lcol + 2][m] = v.z;
            As[lcol + 3][m] = v.w;
        }
        // --- stage B ---
        if (B_ROWS_ARE_N) {
            #pragma unroll
            for (int r = 0; r < 2; ++r) {
                const int n = lrow + r * 64;
                float4 v = *reinterpret_cast<const float4*>(Brow0 + (size_t)n * K + k0 + lcol);
                Bs[lcol + 0][n] = v.x;
                Bs[lcol + 1][n] = v.y;
                Bs[lcol + 2][n] = v.z;
                Bs[lcol + 3][n] = v.w;
            }
        } else {
            #pragma unroll
            for (int r = 0; r < 2; ++r) {
                const int kk = nrow + r * 8;
                float4 v = *reinterpret_cast<const float4*>(
                    Brow0 + (size_t)(k0 + kk) * N + tileN * BN + ncol);
                *reinterpret_cast<float4*>(&Bs[kk][ncol]) = v;
            }
        }
        __syncthreads();

        // --- compute 8x8 micro-tile per thread ---
        #pragma unroll
        for (int kk = 0; kk < BK; ++kk) {
            float af[TM], bf[TN];
            #pragma unroll
            for (int i = 0; i < TM; ++i) af[i] = As[kk][ty * TM + i];
            #pragma unroll
            for (int j = 0; j < TN; ++j) bf[j] = Bs[kk][tx * TN + j];
            #pragma unroll
            for (int i = 0; i < TM; ++i)
                #pragma unroll
                for (int j = 0; j < TN; ++j)
                    acc[i][j] += af[i] * bf[j];
        }
        __syncthreads();
    }

    // --- write back (vectorized) ---
    #pragma unroll
    for (int i = 0; i < TM; ++i) {
        const size_t crow = (size_t)(tileM * BM + ty * TM + i);
        float4* cp = reinterpret_cast<float4*>(C + crow * N + tileN * BN + tx * TN);
        float4 v0 = make_float4(acc[i][0], acc[i][1], acc[i][2], acc[i][3]);
        float4 v1 = make_float4(acc[i][4], acc[i][5], acc[i][6], acc[i][7]);
        cp[0] = v0;
        cp[1] = v1;
    }
}

// ---------------------------------------------------------------------------
// Causal row softmax, in place on g_P. One CTA per row (b*S+m).
// Reads scores[b,m,0..m], writes softmax(scale*scores) there and zeros beyond,
// so the context GEMM needs no masking.
// ---------------------------------------------------------------------------
__global__ __launch_bounds__(256)
void softmax_causal_kernel(float* __restrict__ P, int Sdim)
{
    const int row = blockIdx.x;            // 0 .. B*S-1
    const int m   = row & (Sdim - 1);      // Sdim is a power of two
    float* rp = P + (size_t)row * Sdim;

    __shared__ float buf[S_];
    __shared__ float red[8];

    const int tid  = threadIdx.x;
    const int lane = tid & 31;
    const int wid  = tid >> 5;
    const int L    = m + 1;
    const float scale = 0.03125f;          // 1/sqrt(1024)

    // pass 1: scale, stage to smem, row max
    float mx = -CUDART_INF_F;
    for (int j = tid; j < L; j += 256) {
        float v = rp[j] * scale;
        buf[j] = v;
        mx = fmaxf(mx, v);
    }
    #pragma unroll
    for (int o = 16; o > 0; o >>= 1) mx = fmaxf(mx, __shfl_xor_sync(0xffffffffu, mx, o));
    if (lane == 0) red[wid] = mx;
    __syncthreads();
    float bm = red[0];
    #pragma unroll
    for (int w = 1; w < 8; ++w) bm = fmaxf(bm, red[w]);
    __syncthreads();   // before reusing red[]

    // pass 2: exp + sum
    float sum = 0.0f;
    for (int j = tid; j < L; j += 256) {
        float e = __expf(buf[j] - bm);
        buf[j] = e;
        sum += e;
    }
    #pragma unroll
    for (int o = 16; o > 0; o >>= 1) sum += __shfl_xor_sync(0xffffffffu, sum, o);
    if (lane == 0) red[wid] = sum;
    __syncthreads();
    float tot = 0.0f;
    #pragma unroll
    for (int w = 0; w < 8; ++w) tot += red[w];
    const float inv = 1.0f / tot;

    // pass 3: normalize + zero-fill masked region
    for (int j = tid; j < L; j += 256) rp[j] = buf[j] * inv;
    for (int j = L + tid; j < Sdim; j += 256) rp[j] = 0.0f;
}

// ---------------------------------------------------------------------------
// kernel_launch: x -> Q,K,V (NT GEMMs) -> scores (NT, tri-skip) -> softmax
//                -> context (NN, causal-K) into d_out
// All launches on the default stream; no sync, no allocation.
// ---------------------------------------------------------------------------
extern "C" void kernel_launch(void* const* d_in, const int* in_sizes, int n_in,
                              void* d_out, int out_size)
{
    (void)in_sizes; (void)n_in; (void)out_size;
    const float* x  = (const float*)d_in[0];
    const float* Wq = (const float*)d_in[1];
    const float* Wk = (const float*)d_in[2];
    const float* Wv = (const float*)d_in[3];
    float* out = (float*)d_out;

    float *Q, *K, *V, *P;
    cudaGetSymbolAddress((void**)&Q, g_Q);
    cudaGetSymbolAddress((void**)&K, g_K);
    cudaGetSymbolAddress((void**)&V, g_V);
    cudaGetSymbolAddress((void**)&P, g_P);

    const dim3 blk(NTHREADS);

    // 1) QKV projections: [M_, D_] = x[M_, D_] @ W^T (NT), W is [D_out, D_in]
    const dim3 gq(D_ / BN, M_ / BM, 1);
    sgemm_kernel<true, false, false><<<gq, blk>>>(x, Wq, Q, M_, D_, D_, 0, 0, 0);
    sgemm_kernel<true, false, false><<<gq, blk>>>(x, Wk, K, M_, D_, D_, 0, 0, 0);
    sgemm_kernel<true, false, false><<<gq, blk>>>(x, Wv, V, M_, D_, D_, 0, 0, 0);

    // 2) scores[b] = Q[b] @ K[b]^T (NT), lower-triangular tiles only
    const dim3 gs(S_ / BN, S_ / BM, B_);
    sgemm_kernel<true, true, false><<<gs, blk>>>(
        Q, K, P, S_, S_, D_,
        (size_t)S_ * D_, (size_t)S_ * D_, (size_t)S_ * S_);

    // 3) causal softmax in place (also zeroes the masked upper region)
    softmax_causal_kernel<<<B_ * S_, 256>>>(P, S_);

    // 4) context[b] = P[b] @ V[b] (NN), K loop truncated at the diagonal
    const dim3 gc(D_ / BN, S_ / BM, B_);
    sgemm_kernel<false, false, true><<<gc, blk>>>(
        P, V, out, S_, D_, S_,
        (size_t)S_ * S_, (size_t)S_ * D_, (size_t)S_ * D_);
}

// round 17
// speedup vs baseline: 1.0007x; 1.0007x over previous
#include <cuda_runtime.h>
#include <math_constants.h>

// Problem constants
constexpr int B_   = 4;
constexpr int S_   = 4096;
constexpr int D_   = 1024;
constexpr int M_   = B_ * S_;      // 16384 fused batch*seq rows for QKV

// GEMM tiling
constexpr int BM = 128;
constexpr int BN = 128;
constexpr int BK = 16;
constexpr int TM = 8;
constexpr int TN = 8;
constexpr int NTHREADS = (BM / TM) * (BN / TN);   // 256

// Static device scratch (allocation-free rule): Q,K,V = 3*64MB, P(scores) = 256MB
__device__ float g_Q[(size_t)M_ * D_];
__device__ float g_K[(size_t)M_ * D_];
__device__ float g_V[(size_t)M_ * D_];
__device__ float g_P[(size_t)B_ * S_ * S_];

// ---------------------------------------------------------------------------
// Generic fp32 SGEMM, C = A * op(B)
//   B_ROWS_ARE_N = true  : B is [N, K] row-major (K contiguous)  -> C=A*B^T (NT)
//   B_ROWS_ARE_N = false : B is [K, N] row-major (N contiguous)  -> C=A*B  (NN)
//   TRI_SKIP  : skip whole tiles strictly above the block diagonal (scores)
//   CAUSAL_K  : truncate K loop at (tileM+1)*BM (context GEMM; P is zero above diag)
// blockIdx.z = batch with element strides sA/sB/sC.
// Requires M%BM==0, N%BN==0, K%BK==0, 16B-aligned rows (all true here).
// ---------------------------------------------------------------------------
template<bool B_ROWS_ARE_N, bool TRI_SKIP, bool CAUSAL_K>
__global__ __launch_bounds__(NTHREADS, 2)
void sgemm_kernel(const float* __restrict__ gA, const float* __restrict__ gB,
                  float* __restrict__ gC,
                  int M, int N, int K,
                  size_t sA, size_t sB, size_t sC)
{
    const int tileN = blockIdx.x;
    const int tileM = blockIdx.y;
    if (TRI_SKIP && tileN > tileM) return;   // uniform per-CTA, safe before syncs

    const float* A = gA + (size_t)blockIdx.z * sA;
    const float* Bm = gB + (size_t)blockIdx.z * sB;
    float*       C = gC + (size_t)blockIdx.z * sC;

    int Keff = K;
    if (CAUSAL_K) {
        int lim = (tileM + 1) * BM;
        if (lim < Keff) Keff = lim;
    }

    __shared__ float As[BK][BM];
    __shared__ float Bs[BK][BN];

    const int tid = threadIdx.x;
    const int tx  = tid % (BN / TN);   // 0..15
    const int ty  = tid / (BN / TN);   // 0..15

    // K-major tile load mapping (A always; B when B_ROWS_ARE_N)
    const int lrow = tid >> 2;         // 0..63
    const int lcol = (tid & 3) * 4;    // 0,4,8,12

    // N-contiguous B load mapping (NN mode)
    const int nrow = tid >> 5;         // 0..7
    const int ncol = (tid & 31) * 4;   // 0..124

    const float* Arow0 = A + (size_t)(tileM * BM) * K;
    const float* Brow0 = B_ROWS_ARE_N ? (Bm + (size_t)(tileN * BN) * K) : Bm;

    float acc[TM][TN];
    #pragma unroll
    for (int i = 0; i < TM; ++i)
        #pragma unroll
        for (int j = 0; j < TN; ++j)
            acc[i][j] = 0.0f;

    for (int k0 = 0; k0 < Keff; k0 += BK) {
        // --- stage A (transposed into As[k][m]) ---
        #pragma unroll
        for (int r = 0; r < 2; ++r) {
            const int m = lrow + r * 64;
            float4 v = *reinterpret_cast<const float4*>(Arow0 + (size_t)m * K + k0 + lcol);
            As[lcol + 0][m] = v.x;
            As[lcol + 1][m] = v.y;
            As[lcol + 2][m] = v.z;
            As[lcol + 3][m] = v.w;
        }
        // --- stage B ---
        if (B_ROWS_ARE_N) {
            #pragma unroll
            for (int r = 0; r < 2; ++r) {
                const int n = lrow + r * 64;
                float4 v = *reinterpret_cast<const float4*>(Brow0 + (size_t)n * K + k0 + lcol);
                Bs[lcol + 0][n] = v.x;
                Bs[lcol + 1][n] = v.y;
                Bs[lcol + 2][n] = v.z;
                Bs[lcol + 3][n] = v.w;
            }
        } else {
            #pragma unroll
            for (int r = 0; r < 2; ++r) {
                const int kk = nrow + r * 8;
                float4 v = *reinterpret_cast<const float4*>(
                    Brow0 + (size_t)(k0 + kk) * N + tileN * BN + ncol);
                *reinterpret_cast<float4*>(&Bs[kk][ncol]) = v;
            }
        }
        __syncthreads();

        // --- compute 8x8 micro-tile per thread ---
        #pragma unroll
        for (int kk = 0; kk < BK; ++kk) {
            float af[TM], bf[TN];
            #pragma unroll
            for (int i = 0; i < TM; ++i) af[i] = As[kk][ty * TM + i];
            #pragma unroll
            for (int j = 0; j < TN; ++j) bf[j] = Bs[kk][tx * TN + j];
            #pragma unroll
            for (int i = 0; i < TM; ++i)
                #pragma unroll
                for (int j = 0; j < TN; ++j)
                    acc[i][j] += af[i] * bf[j];
        }
        __syncthreads();
    }

    // --- write back (vectorized) ---
    #pragma unroll
    for (int i = 0; i < TM; ++i) {
        const size_t crow = (size_t)(tileM * BM + ty * TM + i);
        float4* cp = reinterpret_cast<float4*>(C + crow * N + tileN * BN + tx * TN);
        float4 v0 = make_float4(acc[i][0], acc[i][1], acc[i][2], acc[i][3]);
        float4 v1 = make_float4(acc[i][4], acc[i][5], acc[i][6], acc[i][7]);
        cp[0] = v0;
        cp[1] = v1;
    }
}

// ---------------------------------------------------------------------------
// Causal row softmax, in place on g_P. One CTA per row (b*S+m).
// Reads scores[b,m,0..m], writes softmax(scale*scores) there and zeros beyond,
// so the context GEMM needs no masking.
// ---------------------------------------------------------------------------
__global__ __launch_bounds__(256)
void softmax_causal_kernel(float* __restrict__ P, int Sdim)
{
    const int row = blockIdx.x;            // 0 .. B*S-1
    const int m   = row & (Sdim - 1);      // Sdim is a power of two
    float* rp = P + (size_t)row * Sdim;

    __shared__ float buf[S_];
    __shared__ float red[8];

    const int tid  = threadIdx.x;
    const int lane = tid & 31;
    const int wid  = tid >> 5;
    const int L    = m + 1;
    const float scale = 0.03125f;          // 1/sqrt(1024)

    // pass 1: scale, stage to smem, row max
    float mx = -CUDART_INF_F;
    for (int j = tid; j < L; j += 256) {
        float v = rp[j] * scale;
        buf[j] = v;
        mx = fmaxf(mx, v);
    }
    #pragma unroll
    for (int o = 16; o > 0; o >>= 1) mx = fmaxf(mx, __shfl_xor_sync(0xffffffffu, mx, o));
    if (lane == 0) red[wid] = mx;
    __syncthreads();
    float bm = red[0];
    #pragma unroll
    for (int w = 1; w < 8; ++w) bm = fmaxf(bm, red[w]);
    __syncthreads();   // before reusing red[]

    // pass 2: exp + sum
    float sum = 0.0f;
    for (int j = tid; j < L; j += 256) {
        float e = __expf(buf[j] - bm);
        buf[j] = e;
        sum += e;
    }
    #pragma unroll
    for (int o = 16; o > 0; o >>= 1) sum += __shfl_xor_sync(0xffffffffu, sum, o);
    if (lane == 0) red[wid] = sum;
    __syncthreads();
    float tot = 0.0f;
    #pragma unroll
    for (int w = 0; w < 8; ++w) tot += red[w];
    const float inv = 1.0f / tot;

    // pass 3: normalize + zero-fill masked region
    for (int j = tid; j < L; j += 256) rp[j] = buf[j] * inv;
    for (int j = L + tid; j < Sdim; j += 256) rp[j] = 0.0f;
}

// ---------------------------------------------------------------------------
// kernel_launch: x -> Q,K,V (NT GEMMs) -> scores (NT, tri-skip) -> softmax
//                -> context (NN, causal-K) into d_out
// All launches on the default stream; no sync, no allocation.
// ---------------------------------------------------------------------------
extern "C" void kernel_launch(void* const* d_in, const int* in_sizes, int n_in,
                              void* d_out, int out_size)
{
    (void)in_sizes; (void)n_in; (void)out_size;
    const float* x  = (const float*)d_in[0];
    const float* Wq = (const float*)d_in[1];
    const float* Wk = (const float*)d_in[2];
    const float* Wv = (const float*)d_in[3];
    float* out = (float*)d_out;

    float *Q, *K, *V, *P;
    cudaGetSymbolAddress((void**)&Q, g_Q);
    cudaGetSymbolAddress((void**)&K, g_K);
    cudaGetSymbolAddress((void**)&V, g_V);
    cudaGetSymbolAddress((void**)&P, g_P);

    const dim3 blk(NTHREADS);

    // 1) QKV projections: [M_, D_] = x[M_, D_] @ W^T (NT), W is [D_out, D_in]
    const dim3 gq(D_ / BN, M_ / BM, 1);
    sgemm_kernel<true, false, false><<<gq, blk>>>(x, Wq, Q, M_, D_, D_, 0, 0, 0);
    sgemm_kernel<true, false, false><<<gq, blk>>>(x, Wk, K, M_, D_, D_, 0, 0, 0);
    sgemm_kernel<true, false, false><<<gq, blk>>>(x, Wv, V, M_, D_, D_, 0, 0, 0);

    // 2) scores[b] = Q[b] @ K[b]^T (NT), lower-triangular tiles only
    const dim3 gs(S_ / BN, S_ / BM, B_);
    sgemm_kernel<true, true, false><<<gs, blk>>>(
        Q, K, P, S_, S_, D_,
        (size_t)S_ * D_, (size_t)S_ * D_, (size_t)S_ * S_);

    // 3) causal softmax in place (also zeroes the masked upper region)
    softmax_causal_kernel<<<B_ * S_, 256>>>(P, S_);

    // 4) context[b] = P[b] @ V[b] (NN), K loop truncated at the diagonal
    const dim3 gc(D_ / BN, S_ / BM, B_);
    sgemm_kernel<false, false, true><<<gc, blk>>>(
        P, V, out, S_, D_, S_,
        (size_t)S_ * S_, (size_t)S_ * D_, (size_t)S_ * D_);
}